// round 2
// baseline (speedup 1.0000x reference)
#include <cuda_runtime.h>
#include <math.h>

// Problem constants (from reference)
#define NT     128          // N_THETA
#define NP     64           // N_PHI
#define NCELL  8192         // NT*NP
#define NBATCH 16
#define STEPS  10
#define STRIDE 65           // padded smem row stride (65 mod 32 == 1 -> conflict-free)
#define THREADS 512
#define CPT    16           // cells per thread (one quarter of a phi-row)

// Scratch for per-direction weighted-sum accumulators: [dir][batch][cell]
__device__ float g_acc[2][NBATCH][NCELL];

extern __shared__ float sbuf[];   // 2 * NT * STRIDE floats (double-buffered state)

__global__ void __launch_bounds__(THREADS, 1)
prop_kernel(const float* __restrict__ entry,
            const float* __restrict__ sw_f, const float* __restrict__ dec_f,
            const float* __restrict__ sw_r, const float* __restrict__ dec_r,
            const float* __restrict__ bounce)
{
    const int b    = blockIdx.x >> 1;
    const int dir  = blockIdx.x & 1;
    const int tid  = threadIdx.x;
    const int t    = tid & (NT - 1);   // theta row (lanes of a warp = consecutive rows)
    const int chunk = tid >> 7;        // 0..3
    const int p0   = chunk * CPT;

    // ---- scalars: decay clamp + softmax of step weights ----
    const float* sw = dir ? sw_r : sw_f;
    float decay = dir ? dec_r[0] : dec_f[0];
    decay = fminf(fmaxf(decay, 0.5f), 0.99f);

    float w[STEPS];
    float m = -3.402823e38f;
    #pragma unroll
    for (int s = 0; s < STEPS; s++) { w[s] = sw[s]; m = fmaxf(m, w[s]); }
    float sum = 0.f;
    #pragma unroll
    for (int s = 0; s < STEPS; s++) { w[s] = expf(w[s] - m); sum += w[s]; }
    float inv = 1.0f / sum;
    #pragma unroll
    for (int s = 0; s < STEPS; s++) w[s] *= inv;

    // ---- per-owned-cell registers: state, accumulator, angle factor ----
    float st[CPT], acc[CPT], af[CPT];
    const float* e = entry + (size_t)b * NCELL + t * NP + p0;
    #pragma unroll
    for (int k = 0; k < CPT; k++) {
        st[k]  = e[k];
        acc[k] = 0.0f;
        int cell = t * NP + p0 + k;
        float a0 = fabsf(bounce[cell * 3 + 0]);
        float a1 = fabsf(bounce[cell * 3 + 1]);
        float a2 = fabsf(bounce[cell * 3 + 2]);
        af[k] = 0.5f + 0.5f * cosf((a0 + a1 + a2) * (1.0f / 3.0f));
    }

    float* buf0 = sbuf;
    float* buf1 = sbuf + NT * STRIDE;

    #pragma unroll
    for (int k = 0; k < CPT; k++) buf0[t * STRIDE + p0 + k] = st[k];
    __syncthreads();

    float* cur = buf0;
    float* nxt = buf1;

    const float third = 1.0f / 3.0f;   // exact f32 row-normalization of the adjacency

    if (dir == 0) {
        // forward: prop(t,p) = (s[t-1,p] + s[t,p-1] + s[t-1,p-1]) / 3
        const int tm1 = (t + NT - 1) & (NT - 1);
        for (int step = 0; step < STEPS; step++) {
            float up[CPT + 1];
            up[0] = cur[tm1 * STRIDE + ((p0 + NP - 1) & (NP - 1))];   // (t-1, p0-1)
            #pragma unroll
            for (int k = 0; k < CPT; k++)
                up[k + 1] = cur[tm1 * STRIDE + p0 + k];               // (t-1, p0..p0+15)
            float left = cur[t * STRIDE + ((p0 + NP - 1) & (NP - 1))]; // (t, p0-1) OLD value

            float ws = w[step];
            float prev_old = left;   // OLD state of (t, p-1), carried across k
            #pragma unroll
            for (int k = 0; k < CPT; k++) {
                float n_uw = up[k];          // (t-1, p-1)
                float n_u  = up[k + 1];      // (t-1, p)
                float n_w  = prev_old;       // (t,   p-1) -- pre-update value (Jacobi!)
                float prop = (n_u + n_w + n_uw) * third * af[k];
                float sn   = (0.3f * st[k] + 0.7f * prop) * decay;
                acc[k]   = fmaf(ws, sn, acc[k]);
                prev_old = st[k];            // save OLD value before overwrite
                st[k]    = sn;
            }
            #pragma unroll
            for (int k = 0; k < CPT; k++) nxt[t * STRIDE + p0 + k] = st[k];
            __syncthreads();
            float* tmp = cur; cur = nxt; nxt = tmp;
        }
    } else {
        // reverse: prop(t,p) = (s[t+1,p] + s[t,p+1] + s[t+1,p+1]) / 3
        const int tp1 = (t + 1) & (NT - 1);
        for (int step = 0; step < STEPS; step++) {
            float dn[CPT + 1];
            #pragma unroll
            for (int k = 0; k < CPT; k++)
                dn[k] = cur[tp1 * STRIDE + p0 + k];                    // (t+1, p0..p0+15)
            dn[CPT] = cur[tp1 * STRIDE + ((p0 + CPT) & (NP - 1))];     // (t+1, p0+16)
            float right = cur[t * STRIDE + ((p0 + CPT) & (NP - 1))];   // (t,   p0+16)

            float ws = w[step];
            #pragma unroll
            for (int k = 0; k < CPT; k++) {
                float n_d  = dn[k];                             // (t+1, p)
                float n_de = dn[k + 1];                         // (t+1, p+1)
                // ascending k: st[k+1] has NOT been updated yet -> old value (Jacobi-safe)
                float n_e  = (k == CPT - 1) ? right : st[k + 1];// (t,   p+1)
                float prop = (n_d + n_e + n_de) * third * af[k];
                float sn   = (0.3f * st[k] + 0.7f * prop) * decay;
                acc[k] = fmaf(ws, sn, acc[k]);
                st[k]  = sn;
            }
            #pragma unroll
            for (int k = 0; k < CPT; k++) nxt[t * STRIDE + p0 + k] = st[k];
            __syncthreads();
            float* tmp = cur; cur = nxt; nxt = tmp;
        }
    }

    // store this direction's weighted accumulation
    float* out = &g_acc[dir][b][t * NP + p0];
    #pragma unroll
    for (int k = 0; k < CPT; k++) out[k] = acc[k];
}

__global__ void combine_kernel(const float* __restrict__ iw, float* __restrict__ out)
{
    int i = blockIdx.x * blockDim.x + threadIdx.x;
    if (i >= NBATCH * NCELL) return;
    const float* f_acc = &g_acc[0][0][0];
    const float* r_acc = &g_acc[1][0][0];
    float f = f_acc[i];
    float r = r_acc[i];
    float inter = f * r;
    float sg = 1.0f / (1.0f + expf(-iw[0]));
    out[i] = f + r + sg * inter;                 // combined
    out[NBATCH * NCELL + i] = inter;             // interaction
}

extern "C" void kernel_launch(void* const* d_in, const int* in_sizes, int n_in,
                              void* d_out, int out_size)
{
    (void)in_sizes; (void)n_in; (void)out_size;
    const float* entry  = (const float*)d_in[0];
    // d_in[1], d_in[2] are the dense adjacency matrices: structurally a fixed
    // 3-point toroidal stencil with exact f32 weight 1/3 — not read.
    const float* sw_f   = (const float*)d_in[3];
    const float* dec_f  = (const float*)d_in[4];
    const float* sw_r   = (const float*)d_in[5];
    const float* dec_r  = (const float*)d_in[6];
    const float* iw     = (const float*)d_in[7];
    const float* bounce = (const float*)d_in[8];

    const int smem_bytes = 2 * NT * STRIDE * (int)sizeof(float);  // 66560 B
    cudaFuncSetAttribute(prop_kernel, cudaFuncAttributeMaxDynamicSharedMemorySize, smem_bytes);

    prop_kernel<<<2 * NBATCH, THREADS, smem_bytes>>>(entry, sw_f, dec_f, sw_r, dec_r, bounce);
    combine_kernel<<<(NBATCH * NCELL + 255) / 256, 256>>>(iw, (float*)d_out);
}

// round 3
// speedup vs baseline: 2.4442x; 2.4442x over previous
#include <cuda_runtime.h>
#include <math.h>
#include <stdint.h>

// Problem constants
#define NT     128          // N_THETA
#define NP     64           // N_PHI
#define NCELL  8192         // NT*NP
#define NBATCH 16
#define STEPS  10

// Decomposition: 4 CTAs per (batch,dir) along theta; each owns 32 rows,
// computes 16 extra halo rows on the dependency side (>= 10 steps deep).
#define OWN    32
#define HALO   16
#define ROWS   48           // OWN + HALO computed rows
#define S      65           // smem row stride (floats)
#define THREADS 384         // 48 rows * 8 phi-chunks of 8 cells
#define CPT    8            // phi cells per thread

__global__ void __cluster_dims__(2, 1, 1) __launch_bounds__(THREADS, 1)
lattice_fused_kernel(const float* __restrict__ entry,
                     const float* __restrict__ sw_f, const float* __restrict__ dec_f,
                     const float* __restrict__ sw_r, const float* __restrict__ dec_r,
                     const float* __restrict__ iw,  const float* __restrict__ bounce,
                     float* __restrict__ out)
{
    // grid = (2, 4, 16): x = dir (cluster pair), y = theta quadrant, z = batch
    const int dir = blockIdx.x;          // == cluster_ctarank (cluster dims (2,1,1))
    const int q   = blockIdx.y;
    const int b   = blockIdx.z;
    const int tid = threadIdx.x;
    const int r   = tid >> 3;            // local computed row 0..47
    const int p0  = (tid & 7) * CPT;     // phi chunk start

    // forward needs theta-1 side halo (rows below); reverse needs theta+1 side
    const int rowbase = (dir == 0) ? ((32 * q - HALO + NT) & (NT - 1)) : (32 * q);
    const int gr = (rowbase + r) & (NT - 1);   // global theta row of this thread

    __shared__ float buf[2][ROWS * S];   // double-buffered state, 24960 B

    // ---- scalars: decay clamp + softmax of step weights ----
    const float* sw = dir ? sw_r : sw_f;
    float decay = dir ? dec_r[0] : dec_f[0];
    decay = fminf(fmaxf(decay, 0.5f), 0.99f);

    float w[STEPS];
    float m = -3.402823e38f;
    #pragma unroll
    for (int s = 0; s < STEPS; s++) { w[s] = sw[s]; m = fmaxf(m, w[s]); }
    float sum = 0.f;
    #pragma unroll
    for (int s = 0; s < STEPS; s++) { w[s] = __expf(w[s] - m); sum += w[s]; }
    float inv = 1.0f / sum;
    #pragma unroll
    for (int s = 0; s < STEPS; s++) w[s] *= inv;

    const float c2 = 0.3f * decay;                        // old-state coefficient
    const float q3 = 0.7f * decay * (1.0f / 3.0f);        // stencil-sum coefficient

    // ---- per-cell registers: state, accumulator, fused angle coefficient ----
    float st[CPT], acc[CPT], c1[CPT];
    {
        const float4* e4 = (const float4*)(entry + (size_t)b * NCELL + gr * NP + p0);
        float4 v0 = e4[0], v1 = e4[1];
        st[0]=v0.x; st[1]=v0.y; st[2]=v0.z; st[3]=v0.w;
        st[4]=v1.x; st[5]=v1.y; st[6]=v1.z; st[7]=v1.w;
    }
    #pragma unroll
    for (int k = 0; k < CPT; k++) {
        acc[k] = 0.0f;
        int cell = gr * NP + p0 + k;
        float a0 = fabsf(bounce[cell * 3 + 0]);
        float a1 = fabsf(bounce[cell * 3 + 1]);
        float a2 = fabsf(bounce[cell * 3 + 2]);
        float af = 0.5f + 0.5f * __cosf((a0 + a1 + a2) * (1.0f / 3.0f));
        c1[k] = af * q3;
    }

    #pragma unroll
    for (int k = 0; k < CPT; k++) buf[0][r * S + p0 + k] = st[k];
    __syncthreads();

    int cb = 0;
    if (dir == 0) {
        // forward: prop(t,p) ~ s[t-1,p] + s[t,p-1] + s[t-1,p-1]
        const int rm1 = (r > 0) ? (r - 1) : 0;   // clamped: row-0 garbage stays in halo
        const int pm1 = (p0 + NP - 1) & (NP - 1);
        for (int step = 0; step < STEPS; step++) {
            const float* cu = buf[cb];
            float*       nx = buf[cb ^ 1];
            float up[CPT + 1];
            up[0] = cu[rm1 * S + pm1];
            #pragma unroll
            for (int k = 0; k < CPT; k++) up[k + 1] = cu[rm1 * S + p0 + k];
            float prev = cu[r * S + pm1];         // OLD (t, p0-1)
            float ws = w[step];
            #pragma unroll
            for (int k = 0; k < CPT; k++) {
                float sum3 = (up[k + 1] + prev) + up[k];
                float sn   = fmaf(c2, st[k], c1[k] * sum3);
                acc[k] = fmaf(ws, sn, acc[k]);
                prev   = st[k];                   // OLD value (Jacobi)
                st[k]  = sn;
                nx[r * S + p0 + k] = sn;
            }
            __syncthreads();
            cb ^= 1;
        }
    } else {
        // reverse: prop(t,p) ~ s[t+1,p] + s[t,p+1] + s[t+1,p+1]
        const int rp1 = (r < ROWS - 1) ? (r + 1) : (ROWS - 1);
        const int pp8 = (p0 + CPT) & (NP - 1);
        for (int step = 0; step < STEPS; step++) {
            const float* cu = buf[cb];
            float*       nx = buf[cb ^ 1];
            float dn[CPT + 1];
            #pragma unroll
            for (int k = 0; k < CPT; k++) dn[k] = cu[rp1 * S + p0 + k];
            dn[CPT] = cu[rp1 * S + pp8];
            float right = cu[r * S + pp8];        // OLD (t, p0+8)
            float ws = w[step];
            #pragma unroll
            for (int k = 0; k < CPT; k++) {
                float n_e  = (k == CPT - 1) ? right : st[k + 1];  // untouched -> OLD
                float sum3 = (dn[k] + n_e) + dn[k + 1];
                float sn   = fmaf(c2, st[k], c1[k] * sum3);
                acc[k] = fmaf(ws, sn, acc[k]);
                st[k]  = sn;
                nx[r * S + p0 + k] = sn;
            }
            __syncthreads();
            cb ^= 1;
        }
    }

    // ---- exchange accumulators with the paired CTA (other direction) ----
    float* sacc = buf[0];                 // reuse buffer as [OWN][64] acc region
    const int o = (dir == 0) ? (r - HALO) : r;          // owned output row index
    const bool owned = (o >= 0) && (o < OWN);
    if (owned) {
        #pragma unroll
        for (int k = 0; k < CPT; k++) sacc[o * NP + p0 + k] = acc[k];
    }
    __syncthreads();
    asm volatile("barrier.cluster.arrive.aligned;" ::: "memory");
    asm volatile("barrier.cluster.wait.aligned;"   ::: "memory");

    if (owned) {
        uint32_t laddr;
        {
            const void* p = (const void*)(sacc + o * NP + p0);
            asm("{ .reg .u64 t; cvta.to.shared.u64 t, %1; cvt.u32.u64 %0, t; }"
                : "=r"(laddr) : "l"(p));
        }
        uint32_t raddr;
        asm("mapa.shared::cluster.u32 %0, %1, %2;" : "=r"(raddr) : "r"(laddr), "r"(dir ^ 1));
        float other[CPT];
        #pragma unroll
        for (int k = 0; k < CPT; k++) {
            asm volatile("ld.shared::cluster.f32 %0, [%1];"
                         : "=f"(other[k]) : "r"(raddr + 4u * k));
        }
        const int grow = 32 * q + o;
        if (dir == 0) {
            // mine = f, other = r  -> write combined
            float sg = 1.0f / (1.0f + __expf(-iw[0]));
            float* dst = out + (size_t)b * NCELL + grow * NP + p0;
            #pragma unroll
            for (int k = 0; k < CPT; k++) {
                float inter = acc[k] * other[k];
                dst[k] = acc[k] + other[k] + sg * inter;
            }
        } else {
            // mine = r, other = f  -> write interaction
            float* dst = out + (size_t)NBATCH * NCELL + (size_t)b * NCELL + grow * NP + p0;
            #pragma unroll
            for (int k = 0; k < CPT; k++) dst[k] = other[k] * acc[k];
        }
    }

    // keep SMEM alive until the peer has finished reading it
    asm volatile("barrier.cluster.arrive.aligned;" ::: "memory");
    asm volatile("barrier.cluster.wait.aligned;"   ::: "memory");
}

extern "C" void kernel_launch(void* const* d_in, const int* in_sizes, int n_in,
                              void* d_out, int out_size)
{
    (void)in_sizes; (void)n_in; (void)out_size;
    const float* entry  = (const float*)d_in[0];
    // d_in[1], d_in[2]: dense adjacency matrices == fixed 3-point toroidal
    // stencil with exact f32 weight 1/3 — not read.
    const float* sw_f   = (const float*)d_in[3];
    const float* dec_f  = (const float*)d_in[4];
    const float* sw_r   = (const float*)d_in[5];
    const float* dec_r  = (const float*)d_in[6];
    const float* iw     = (const float*)d_in[7];
    const float* bounce = (const float*)d_in[8];

    dim3 grid(2, 4, NBATCH);   // 128 CTAs = 64 clusters of (fwd, rev)
    lattice_fused_kernel<<<grid, THREADS>>>(entry, sw_f, dec_f, sw_r, dec_r,
                                            iw, bounce, (float*)d_out);
}

// round 4
// speedup vs baseline: 3.4112x; 1.3956x over previous
#include <cuda_runtime.h>
#include <math.h>
#include <stdint.h>

// Problem constants
#define NT     128          // N_THETA
#define NP     64           // N_PHI
#define NCELL  8192         // NT*NP
#define NBATCH 16
#define STEPS  10

// Decomposition: 8 theta-slices per (batch); each CTA handles BOTH directions
// as two independent 256-thread halves. Each half owns 16 rows and computes
// 16 halo rows on its dependency side (>= 10 steps deep -> zero communication).
#define OWN    16
#define HALO   16
#define ROWS   32           // OWN + HALO computed rows per half
#define S      65           // smem row stride (65 mod 32 == 1 -> conflict-free)
#define THREADS 512         // 2 halves x (32 rows * 8 phi-chunks)
#define HALF   256
#define CPT    8            // phi cells per thread

__global__ void __launch_bounds__(THREADS, 1)
lattice_fused_kernel(const float* __restrict__ entry,
                     const float* __restrict__ sw_f, const float* __restrict__ dec_f,
                     const float* __restrict__ sw_r, const float* __restrict__ dec_r,
                     const float* __restrict__ iw,  const float* __restrict__ bounce,
                     float* __restrict__ out)
{
    // grid = (8, 16): x = theta slice, y = batch
    const int q   = blockIdx.x;
    const int b   = blockIdx.y;
    const int tid = threadIdx.x;
    const int dir = tid >> 8;            // 0 = forward half, 1 = reverse half
    const int lt  = tid & (HALF - 1);
    const int r   = lt >> 3;             // local computed row 0..31
    const int p0  = (lt & 7) * CPT;      // phi chunk start

    // forward needs theta-1 side halo (rows below); reverse needs theta+1 side
    const int rowbase = (dir == 0) ? ((OWN * q - HALO + NT) & (NT - 1)) : (OWN * q);
    const int gr = (rowbase + r) & (NT - 1);   // global theta row

    __shared__ float bufF[2][ROWS * S];  // forward half state (double-buffered)
    __shared__ float bufR[2][ROWS * S];  // reverse half state
    float* bA = dir ? bufR[0] : bufF[0];
    float* bB = dir ? bufR[1] : bufF[1];

    // ---- scalars: decay clamp + softmax of step weights ----
    const float* sw = dir ? sw_r : sw_f;
    float decay = dir ? dec_r[0] : dec_f[0];
    decay = fminf(fmaxf(decay, 0.5f), 0.99f);

    float w[STEPS];
    float m = -3.402823e38f;
    #pragma unroll
    for (int s = 0; s < STEPS; s++) { w[s] = sw[s]; m = fmaxf(m, w[s]); }
    float sum = 0.f;
    #pragma unroll
    for (int s = 0; s < STEPS; s++) { w[s] = __expf(w[s] - m); sum += w[s]; }
    float inv = 1.0f / sum;
    #pragma unroll
    for (int s = 0; s < STEPS; s++) w[s] *= inv;

    const float c2 = 0.3f * decay;                    // old-state coefficient
    const float q3 = 0.7f * decay * (1.0f / 3.0f);    // stencil-sum coefficient

    // ---- per-cell registers: state, accumulator, fused angle coefficient ----
    float st[CPT], acc[CPT], c1[CPT];
    {
        const float4* e4 = (const float4*)(entry + (size_t)b * NCELL + gr * NP + p0);
        float4 v0 = e4[0], v1 = e4[1];
        st[0]=v0.x; st[1]=v0.y; st[2]=v0.z; st[3]=v0.w;
        st[4]=v1.x; st[5]=v1.y; st[6]=v1.z; st[7]=v1.w;
    }
    {
        // bounce for 8 consecutive cells = 24 contiguous floats, 96B-aligned
        const float4* b4 = (const float4*)(bounce + (size_t)(gr * NP + p0) * 3);
        float4 v0 = b4[0], v1 = b4[1], v2 = b4[2];
        float4 v3 = b4[3], v4 = b4[4], v5 = b4[5];
        float a[24] = { v0.x,v0.y,v0.z,v0.w, v1.x,v1.y,v1.z,v1.w,
                        v2.x,v2.y,v2.z,v2.w, v3.x,v3.y,v3.z,v3.w,
                        v4.x,v4.y,v4.z,v4.w, v5.x,v5.y,v5.z,v5.w };
        #pragma unroll
        for (int k = 0; k < CPT; k++) {
            float s3 = fabsf(a[3*k]) + fabsf(a[3*k+1]) + fabsf(a[3*k+2]);
            float af = 0.5f + 0.5f * __cosf(s3 * (1.0f / 3.0f));
            c1[k] = af * q3;
            acc[k] = 0.0f;
        }
    }

    #pragma unroll
    for (int k = 0; k < CPT; k++) bA[r * S + p0 + k] = st[k];

    // per-half named barriers: id 1 = forward half, id 2 = reverse half
    #define HBAR() asm volatile("bar.sync %0, 256;" :: "r"(1 + dir) : "memory")
    HBAR();

    int cb = 0;
    if (dir == 0) {
        // forward: prop(t,p) ~ s[t-1,p] + s[t,p-1] + s[t-1,p-1]
        const int rm1 = (r > 0) ? (r - 1) : 0;   // clamp: garbage stays in halo
        const int pm1 = (p0 + NP - 1) & (NP - 1);
        for (int step = 0; step < STEPS; step++) {
            const float* cu = cb ? bB : bA;
            float*       nx = cb ? bA : bB;
            float up[CPT + 1];
            up[0] = cu[rm1 * S + pm1];
            #pragma unroll
            for (int k = 0; k < CPT; k++) up[k + 1] = cu[rm1 * S + p0 + k];
            float prev = cu[r * S + pm1];         // OLD (t, p0-1)
            float ws = w[step];
            #pragma unroll
            for (int k = 0; k < CPT; k++) {
                float sum3 = (up[k + 1] + prev) + up[k];
                float sn   = fmaf(c2, st[k], c1[k] * sum3);
                acc[k] = fmaf(ws, sn, acc[k]);
                prev   = st[k];                   // OLD value (Jacobi)
                st[k]  = sn;
                nx[r * S + p0 + k] = sn;
            }
            HBAR();
            cb ^= 1;
        }
    } else {
        // reverse: prop(t,p) ~ s[t+1,p] + s[t,p+1] + s[t+1,p+1]
        const int rp1 = (r < ROWS - 1) ? (r + 1) : (ROWS - 1);
        const int pp8 = (p0 + CPT) & (NP - 1);
        for (int step = 0; step < STEPS; step++) {
            const float* cu = cb ? bB : bA;
            float*       nx = cb ? bA : bB;
            float dn[CPT + 1];
            #pragma unroll
            for (int k = 0; k < CPT; k++) dn[k] = cu[rp1 * S + p0 + k];
            dn[CPT] = cu[rp1 * S + pp8];
            float right = cu[r * S + pp8];        // OLD (t, p0+8)
            float ws = w[step];
            #pragma unroll
            for (int k = 0; k < CPT; k++) {
                float n_e  = (k == CPT - 1) ? right : st[k + 1];  // untouched -> OLD
                float sum3 = (dn[k] + n_e) + dn[k + 1];
                float sn   = fmaf(c2, st[k], c1[k] * sum3);
                acc[k] = fmaf(ws, sn, acc[k]);
                st[k]  = sn;
                nx[r * S + p0 + k] = sn;
            }
            HBAR();
            cb ^= 1;
        }
    }

    // ---- cross-direction combine through SMEM (no clusters, no 2nd kernel) ----
    // Each half parks its accumulator in its own buffer[0] region.
    const int o = (dir == 0) ? (r - HALO) : r;    // owned output row index
    const bool owned = (o >= 0) && (o < OWN);
    float* myacc = dir ? bufR[0] : bufF[0];
    if (owned) {
        #pragma unroll
        for (int k = 0; k < CPT; k++) myacc[o * NP + p0 + k] = acc[k];
    }
    __syncthreads();

    if (owned) {
        const float* otacc = dir ? bufF[0] : bufR[0];
        float other[CPT];
        #pragma unroll
        for (int k = 0; k < CPT; k++) other[k] = otacc[o * NP + p0 + k];
        const int grow = OWN * q + o;
        if (dir == 0) {
            // mine = f, other = r -> write combined
            float sg = 1.0f / (1.0f + __expf(-iw[0]));
            float4* dst = (float4*)(out + (size_t)b * NCELL + grow * NP + p0);
            float v[CPT];
            #pragma unroll
            for (int k = 0; k < CPT; k++)
                v[k] = acc[k] + other[k] + sg * (acc[k] * other[k]);
            dst[0] = make_float4(v[0], v[1], v[2], v[3]);
            dst[1] = make_float4(v[4], v[5], v[6], v[7]);
        } else {
            // mine = r, other = f -> write interaction
            float4* dst = (float4*)(out + (size_t)NBATCH * NCELL
                                        + (size_t)b * NCELL + grow * NP + p0);
            float v[CPT];
            #pragma unroll
            for (int k = 0; k < CPT; k++) v[k] = other[k] * acc[k];
            dst[0] = make_float4(v[0], v[1], v[2], v[3]);
            dst[1] = make_float4(v[4], v[5], v[6], v[7]);
        }
    }
}

extern "C" void kernel_launch(void* const* d_in, const int* in_sizes, int n_in,
                              void* d_out, int out_size)
{
    (void)in_sizes; (void)n_in; (void)out_size;
    const float* entry  = (const float*)d_in[0];
    // d_in[1], d_in[2]: dense adjacency matrices == fixed 3-point toroidal
    // stencil with exact f32 weight 1/3 — not read.
    const float* sw_f   = (const float*)d_in[3];
    const float* dec_f  = (const float*)d_in[4];
    const float* sw_r   = (const float*)d_in[5];
    const float* dec_r  = (const float*)d_in[6];
    const float* iw     = (const float*)d_in[7];
    const float* bounce = (const float*)d_in[8];

    dim3 grid(8, NBATCH);   // 128 CTAs, one wave
    lattice_fused_kernel<<<grid, THREADS>>>(entry, sw_f, dec_f, sw_r, dec_r,
                                            iw, bounce, (float*)d_out);
}

// round 5
// speedup vs baseline: 3.6745x; 1.0772x over previous
#include <cuda_runtime.h>
#include <math.h>
#include <stdint.h>

// Problem constants
#define NT     128          // N_THETA
#define NP     64           // N_PHI
#define NCELL  8192         // NT*NP
#define NBATCH 16
#define STEPS  10

// Decomposition: 8 theta-slices per batch; each CTA = two independent
// 256-thread halves (fwd / rev). Each half owns 16 rows + 16 halo rows on its
// dependency side; the trapezoid predicate skips halo rows that can no longer
// influence the owned region.
#define OWN    16
#define HALO   16
#define ROWS   32
#define S      69           // smem row stride; with chunk offset -> conflict-free
#define THREADS 512
#define HALF   256
#define CPT    8

// phi -> smem column: +4 float offset for chunks >= 4 kills the
// (c, c+4) 2-way bank collision present with a plain stride.
__device__ __forceinline__ int colof(int p) { return p + ((p >> 5) << 2); }

__global__ void __launch_bounds__(THREADS, 1)
lattice_fused_kernel(const float* __restrict__ entry,
                     const float* __restrict__ sw_f, const float* __restrict__ dec_f,
                     const float* __restrict__ sw_r, const float* __restrict__ dec_r,
                     const float* __restrict__ iw,  const float* __restrict__ bounce,
                     float* __restrict__ out)
{
    // grid = (8, 16): x = theta slice, y = batch
    const int q   = blockIdx.x;
    const int b   = blockIdx.y;
    const int tid = threadIdx.x;
    const int dir = tid >> 8;            // 0 = forward half, 1 = reverse half
    const int lt  = tid & (HALF - 1);
    const int r   = lt >> 3;             // local computed row 0..31
    const int p0  = (lt & 7) * CPT;      // phi chunk start
    const int c0  = colof(p0);           // smem column of chunk start

    // forward: theta-1 halo below owned rows; reverse: theta+1 halo above
    const int rowbase = (dir == 0) ? ((OWN * q - HALO + NT) & (NT - 1)) : (OWN * q);
    const int gr = (rowbase + r) & (NT - 1);   // global theta row

    __shared__ float bufF[2][ROWS * S];
    __shared__ float bufR[2][ROWS * S];
    float* bA = dir ? bufR[0] : bufF[0];
    float* bB = dir ? bufR[1] : bufF[1];

    // ---- scalars: decay clamp + softmax of step weights ----
    const float* sw = dir ? sw_r : sw_f;
    float decay = dir ? dec_r[0] : dec_f[0];
    decay = fminf(fmaxf(decay, 0.5f), 0.99f);

    float w[STEPS];
    float m = -3.402823e38f;
    #pragma unroll
    for (int s = 0; s < STEPS; s++) { w[s] = sw[s]; m = fmaxf(m, w[s]); }
    float sum = 0.f;
    #pragma unroll
    for (int s = 0; s < STEPS; s++) { w[s] = __expf(w[s] - m); sum += w[s]; }
    float inv = 1.0f / sum;
    #pragma unroll
    for (int s = 0; s < STEPS; s++) w[s] *= inv;

    const float c2 = 0.3f * decay;
    const float q3 = 0.7f * decay * (1.0f / 3.0f);

    // owned rows: fwd -> r >= HALO, rev -> r < OWN
    const bool owned = (dir == 0) ? (r >= HALO) : (r < OWN);

    // ---- per-cell registers ----
    float st[CPT], acc[CPT], c1[CPT];
    {
        const float4* e4 = (const float4*)(entry + (size_t)b * NCELL + gr * NP + p0);
        float4 v0 = e4[0], v1 = e4[1];
        st[0]=v0.x; st[1]=v0.y; st[2]=v0.z; st[3]=v0.w;
        st[4]=v1.x; st[5]=v1.y; st[6]=v1.z; st[7]=v1.w;
    }
    {
        const float4* b4 = (const float4*)(bounce + (size_t)(gr * NP + p0) * 3);
        float4 v0 = b4[0], v1 = b4[1], v2 = b4[2];
        float4 v3 = b4[3], v4 = b4[4], v5 = b4[5];
        float a[24] = { v0.x,v0.y,v0.z,v0.w, v1.x,v1.y,v1.z,v1.w,
                        v2.x,v2.y,v2.z,v2.w, v3.x,v3.y,v3.z,v3.w,
                        v4.x,v4.y,v4.z,v4.w, v5.x,v5.y,v5.z,v5.w };
        #pragma unroll
        for (int k = 0; k < CPT; k++) {
            float s3 = fabsf(a[3*k]) + fabsf(a[3*k+1]) + fabsf(a[3*k+2]);
            c1[k] = (0.5f + 0.5f * __cosf(s3 * (1.0f / 3.0f))) * q3;
            acc[k] = 0.0f;
        }
    }

    #pragma unroll
    for (int k = 0; k < CPT; k++) bA[r * S + c0 + k] = st[k];

    #define HBAR() asm volatile("bar.sync %0, 256;" :: "r"(1 + dir) : "memory")
    HBAR();

    int cb = 0;
    if (dir == 0) {
        // forward: prop(t,p) ~ s[t-1,p] + s[t,p-1] + s[t-1,p-1]
        const int rm1 = (r > 0) ? (r - 1) : 0;
        const int cm1 = colof((p0 + NP - 1) & (NP - 1));
        for (int step = 0; step < STEPS; step++) {
            // trapezoid: row r at (1-based) step s=step+1 matters iff r >= s+6
            if (r >= step + 7) {
                const float* cu = cb ? bB : bA;
                float*       nx = cb ? bA : bB;
                float up[CPT + 1];
                up[0] = cu[rm1 * S + cm1];
                #pragma unroll
                for (int k = 0; k < CPT; k++) up[k + 1] = cu[rm1 * S + c0 + k];
                float prev = cu[r * S + cm1];          // OLD (t, p0-1)
                float ws = w[step];
                #pragma unroll
                for (int k = 0; k < CPT; k++) {
                    float sum3 = (up[k + 1] + prev) + up[k];
                    float sn   = fmaf(c2, st[k], c1[k] * sum3);
                    if (owned) acc[k] = fmaf(ws, sn, acc[k]);
                    prev  = st[k];                     // OLD value (Jacobi)
                    st[k] = sn;
                    if (step < STEPS - 1) nx[r * S + c0 + k] = sn;
                }
            }
            if (step < STEPS - 1) { HBAR(); cb ^= 1; }
        }
    } else {
        // reverse: prop(t,p) ~ s[t+1,p] + s[t,p+1] + s[t+1,p+1]
        const int rp1 = (r < ROWS - 1) ? (r + 1) : (ROWS - 1);
        const int cp8 = colof((p0 + CPT) & (NP - 1));
        for (int step = 0; step < STEPS; step++) {
            // trapezoid (mirror): row r matters iff r <= 24 - step
            if (r <= 24 - step) {
                const float* cu = cb ? bB : bA;
                float*       nx = cb ? bA : bB;
                float dn[CPT + 1];
                #pragma unroll
                for (int k = 0; k < CPT; k++) dn[k] = cu[rp1 * S + c0 + k];
                dn[CPT] = cu[rp1 * S + cp8];
                float right = cu[r * S + cp8];         // OLD (t, p0+8)
                float ws = w[step];
                #pragma unroll
                for (int k = 0; k < CPT; k++) {
                    float n_e  = (k == CPT - 1) ? right : st[k + 1];  // OLD
                    float sum3 = (dn[k] + n_e) + dn[k + 1];
                    float sn   = fmaf(c2, st[k], c1[k] * sum3);
                    if (owned) acc[k] = fmaf(ws, sn, acc[k]);
                    st[k] = sn;
                    if (step < STEPS - 1) nx[r * S + c0 + k] = sn;
                }
            }
            if (step < STEPS - 1) { HBAR(); cb ^= 1; }
        }
    }

    // ---- cross-direction combine through SMEM ----
    // Final step read buf[1]; acc parking uses buf[0] -> no extra barrier needed
    // before parking, one __syncthreads() covers the cross-half exchange.
    const int o = (dir == 0) ? (r - HALO) : r;
    float* myacc = dir ? bufR[0] : bufF[0];
    if (owned) {
        #pragma unroll
        for (int k = 0; k < CPT; k++) myacc[o * NP + p0 + k] = acc[k];
    }
    __syncthreads();

    if (owned) {
        const float* otacc = dir ? bufF[0] : bufR[0];
        float other[CPT];
        #pragma unroll
        for (int k = 0; k < CPT; k++) other[k] = otacc[o * NP + p0 + k];
        const int grow = OWN * q + o;
        if (dir == 0) {
            float sg = 1.0f / (1.0f + __expf(-iw[0]));
            float4* dst = (float4*)(out + (size_t)b * NCELL + grow * NP + p0);
            float v[CPT];
            #pragma unroll
            for (int k = 0; k < CPT; k++)
                v[k] = acc[k] + other[k] + sg * (acc[k] * other[k]);
            dst[0] = make_float4(v[0], v[1], v[2], v[3]);
            dst[1] = make_float4(v[4], v[5], v[6], v[7]);
        } else {
            float4* dst = (float4*)(out + (size_t)NBATCH * NCELL
                                        + (size_t)b * NCELL + grow * NP + p0);
            float v[CPT];
            #pragma unroll
            for (int k = 0; k < CPT; k++) v[k] = other[k] * acc[k];
            dst[0] = make_float4(v[0], v[1], v[2], v[3]);
            dst[1] = make_float4(v[4], v[5], v[6], v[7]);
        }
    }
}

extern "C" void kernel_launch(void* const* d_in, const int* in_sizes, int n_in,
                              void* d_out, int out_size)
{
    (void)in_sizes; (void)n_in; (void)out_size;
    const float* entry  = (const float*)d_in[0];
    // d_in[1], d_in[2]: dense adjacency == fixed 3-point toroidal stencil
    // with exact f32 weight 1/3 — not read.
    const float* sw_f   = (const float*)d_in[3];
    const float* dec_f  = (const float*)d_in[4];
    const float* sw_r   = (const float*)d_in[5];
    const float* dec_r  = (const float*)d_in[6];
    const float* iw     = (const float*)d_in[7];
    const float* bounce = (const float*)d_in[8];

    dim3 grid(8, NBATCH);   // 128 CTAs, one wave
    lattice_fused_kernel<<<grid, THREADS>>>(entry, sw_f, dec_f, sw_r, dec_r,
                                            iw, bounce, (float*)d_out);
}